// round 8
// baseline (speedup 1.0000x reference)
#include <cuda_runtime.h>
#include <cuda_bf16.h>
#include <cstdint>
#include <math.h>

// Problem constants
#define Bdim 4
#define Ldim 8192
#define Ddim 512
#define Mdim (Bdim * Ldim)   // 32768
#define Ntot (2 * Ddim)      // 1024
#define Kdim 512

// GEMM tiling (mma.sync tf32, cp.async 3-stage, 2 CTAs/SM)
#define BM 128
#define BN 128
#define BK 32
#define NKT (Kdim / BK)                  // 16
#define A_FLOATS (BM * BK)               // 4096
#define B_FLOATS (BN * BK)               // 4096
#define STAGE_FLOATS (A_FLOATS + B_FLOATS)      // 8192
#define NSTAGES 3
#define SMEM_BYTES (NSTAGES * STAGE_FLOATS * 4) // 98304 -> 2 CTAs/SM

// Scan config
#define CHUNK 64
#define NCHUNK (Ldim / CHUNK)        // 128
#define NCHAN (Bdim * Ddim)          // 2048

// ---------------- scratch ----------------
__device__ float g_gate[(size_t)Mdim * Ddim];
__device__ float c_cand[(size_t)Mdim * Ddim];
__device__ float W_rna[(size_t)Ntot * Kdim];    // [Wg;Wc] rounded to tf32 (rna)
__device__ float2 chunkAB[(size_t)NCHAN * NCHUNK];
__device__ float  chunkH[(size_t)NCHAN * NCHUNK];

// ---------------- helpers ----------------
__device__ __forceinline__ uint32_t smem_u32(const void* p) {
    uint32_t a;
    asm("{ .reg .u64 t; cvta.to.shared.u64 t, %1; cvt.u32.u64 %0, t; }" : "=r"(a) : "l"(p));
    return a;
}
__device__ __forceinline__ uint32_t f2tf32(float x) {
    uint32_t r;
    asm("cvt.rna.tf32.f32 %0, %1;" : "=r"(r) : "f"(x));
    return r;
}
__device__ __forceinline__ void cp16(uint32_t dst, const void* src) {
    asm volatile("cp.async.cg.shared.global [%0], [%1], 16;" :: "r"(dst), "l"(src));
}
__device__ __forceinline__ void cp_commit() { asm volatile("cp.async.commit_group;" ::: "memory"); }
template <int N>
__device__ __forceinline__ void cp_wait() { asm volatile("cp.async.wait_group %0;" :: "n"(N) : "memory"); }

__device__ __forceinline__ void mma_tf32(float c[4], const uint32_t a[4], const uint32_t b[2]) {
    asm volatile(
        "mma.sync.aligned.m16n8k8.row.col.f32.tf32.tf32.f32 "
        "{%0,%1,%2,%3}, {%4,%5,%6,%7}, {%8,%9}, {%0,%1,%2,%3};\n"
        : "+f"(c[0]), "+f"(c[1]), "+f"(c[2]), "+f"(c[3])
        : "r"(a[0]), "r"(a[1]), "r"(a[2]), "r"(a[3]), "r"(b[0]), "r"(b[1]));
}

// XOR-swizzled smem float index (row stride 32 floats / 128B)
__device__ __forceinline__ int swz(int row, int col) {
    return (row << 5) + ((((col >> 2) ^ (row & 7)) << 2) | (col & 3));
}

// ---------------- pre-round W to tf32 (rna) ----------------
__global__ void preround_kernel(const float* __restrict__ Wg, const float* __restrict__ Wc)
{
    int i = blockIdx.x * 256 + threadIdx.x;       // 0..131071 float4 slots
    const int half = (Ntot / 2) * Kdim / 4;       // 65536
    const float4* src = (i < half) ? (const float4*)Wg : (const float4*)Wc;
    int j = (i < half) ? i : i - half;
    float4 v = src[j];
    v.x = __uint_as_float(f2tf32(v.x));
    v.y = __uint_as_float(f2tf32(v.y));
    v.z = __uint_as_float(f2tf32(v.z));
    v.w = __uint_as_float(f2tf32(v.w));
    reinterpret_cast<float4*>(W_rna)[i] = v;
}

// ---------------- fused GEMM + activation ----------------
__global__ __launch_bounds__(256, 2) void gemm_act_kernel(
    const float* __restrict__ x,
    const float* __restrict__ bg, const float* __restrict__ bc)
{
    extern __shared__ float sm[];
    const uint32_t smem_base = smem_u32(sm);

    const int m0 = blockIdx.y * BM;
    const int n0 = blockIdx.x * BN;
    const bool isGate = (n0 < Ddim);
    const float* W = W_rna + (size_t)n0 * Kdim;

    const int tid  = threadIdx.x;
    const int warp = tid >> 5;
    const int lane = tid & 31;
    const int wm = warp >> 2;                // 0..1 -> 64 rows each
    const int wn = warp & 3;                 // 0..3 -> 32 cols each
    const int g  = lane >> 2;
    const int tg = lane & 3;

    // stage loader: A 1024 float4 + B 1024 float4, 256 threads -> 8 cp16/thread
    auto load_stage = [&](int kt) {
        const uint32_t base  = smem_base + (kt % NSTAGES) * (STAGE_FLOATS * 4);
        const uint32_t bbase = base + A_FLOATS * 4;
        const int k0 = kt * BK;
        #pragma unroll
        for (int r = 0; r < 4; ++r) {
            int i = tid + (r << 8);
            int row = i >> 3, j = i & 7;
            cp16(base + 4 * ((row << 5) + ((j ^ (row & 7)) << 2)),
                 x + (size_t)(m0 + row) * Kdim + k0 + j * 4);
        }
        #pragma unroll
        for (int r = 0; r < 4; ++r) {
            int i = tid + (r << 8);
            int row = i >> 3, j = i & 7;
            cp16(bbase + 4 * ((row << 5) + ((j ^ (row & 7)) << 2)),
                 W + (size_t)row * Kdim + k0 + j * 4);
        }
        cp_commit();
    };

    float acc[4][4][4];
    #pragma unroll
    for (int mt = 0; mt < 4; ++mt)
        #pragma unroll
        for (int nt = 0; nt < 4; ++nt)
            #pragma unroll
            for (int i = 0; i < 4; ++i) acc[mt][nt][i] = 0.0f;

    load_stage(0);
    load_stage(1);

    for (int s = 0; s < NKT; ++s) {
        if (s < NKT - 1) cp_wait<1>(); else cp_wait<0>();
        __syncthreads();                       // single barrier per k-tile

        if (s + 2 < NKT) load_stage(s + 2);    // writes slot last read in compute(s-1)

        const float* As = sm + (s % NSTAGES) * STAGE_FLOATS;
        const float* Bs = As + A_FLOATS;
        #pragma unroll
        for (int ks = 0; ks < BK / 8; ++ks) {
            const int k = ks * 8;
            uint32_t af[4][4], bf[4][2];
            #pragma unroll
            for (int mt = 0; mt < 4; ++mt) {
                int r = wm * 64 + mt * 16;
                af[mt][0] = __float_as_uint(As[swz(r + g,     k + tg)]);
                af[mt][1] = __float_as_uint(As[swz(r + g + 8, k + tg)]);
                af[mt][2] = __float_as_uint(As[swz(r + g,     k + tg + 4)]);
                af[mt][3] = __float_as_uint(As[swz(r + g + 8, k + tg + 4)]);
            }
            #pragma unroll
            for (int nt = 0; nt < 4; ++nt) {
                int n = wn * 32 + nt * 8 + g;
                bf[nt][0] = __float_as_uint(Bs[swz(n, k + tg)]);
                bf[nt][1] = __float_as_uint(Bs[swz(n, k + tg + 4)]);
            }
            #pragma unroll
            for (int mt = 0; mt < 4; ++mt)
                #pragma unroll
                for (int nt = 0; nt < 4; ++nt)
                    mma_tf32(acc[mt][nt], af[mt], bf[nt]);
        }
    }

    // epilogue: bias + activation
    float* dst = isGate ? g_gate : c_cand;
    const float* bias = isGate ? bg : bc;
    const int cb = n0 & (Ddim - 1);
    #pragma unroll
    for (int mt = 0; mt < 4; ++mt) {
        #pragma unroll
        for (int nt = 0; nt < 4; ++nt) {
            int row0 = m0 + wm * 64 + mt * 16 + g;
            int col  = cb + wn * 32 + nt * 8 + 2 * tg;
            float b0v = bias[col], b1v = bias[col + 1];
            float2 o0, o1;
            if (isGate) {
                o0.x = 1.0f / (1.0f + expf(-(acc[mt][nt][0] + b0v)));
                o0.y = 1.0f / (1.0f + expf(-(acc[mt][nt][1] + b1v)));
                o1.x = 1.0f / (1.0f + expf(-(acc[mt][nt][2] + b0v)));
                o1.y = 1.0f / (1.0f + expf(-(acc[mt][nt][3] + b1v)));
            } else {
                o0.x = tanhf(acc[mt][nt][0] + b0v);
                o0.y = tanhf(acc[mt][nt][1] + b1v);
                o1.x = tanhf(acc[mt][nt][2] + b0v);
                o1.y = tanhf(acc[mt][nt][3] + b1v);
            }
            *reinterpret_cast<float2*>(&dst[(size_t)row0 * Ddim + col]) = o0;
            *reinterpret_cast<float2*>(&dst[(size_t)(row0 + 8) * Ddim + col]) = o1;
        }
    }
}

// ---------------- scan phase 1: per-chunk composed (A, B) ----------------
__global__ __launch_bounds__(Ddim) void scan_phase1(void)
{
    const int b = blockIdx.x >> 7;               // / NCHUNK
    const int j = blockIdx.x & (NCHUNK - 1);
    const int d = threadIdx.x;
    const size_t base = ((size_t)b * Ldim + (size_t)j * CHUNK) * Ddim + d;
    const float* gp = g_gate + base;
    const float* cp = c_cand + base;

    float A = 1.0f, Bv = 0.0f;
    #pragma unroll 4
    for (int t = 0; t < CHUNK; ++t) {
        float gv = gp[(size_t)t * Ddim];
        float cv = cp[(size_t)t * Ddim];
        float a = 1.0f - gv;
        Bv = fmaf(a, Bv, gv * cv);
        A  = a * A;
    }
    chunkAB[((size_t)b * Ddim + d) * NCHUNK + j] = make_float2(A, Bv);
}

// ---------------- scan phase 2: warp per channel, 128 chunks (4/lane) -----
__global__ __launch_bounds__(256) void scan_phase2(void)
{
    const int warp = threadIdx.x >> 5;
    const int lane = threadIdx.x & 31;
    const int ch = blockIdx.x * 8 + warp;
    const size_t base = (size_t)ch * NCHUNK + 4 * lane;

    float2 v0 = chunkAB[base + 0];
    float2 v1 = chunkAB[base + 1];
    float2 v2 = chunkAB[base + 2];
    float2 v3 = chunkAB[base + 3];
    float2 p01, p23, p;
    p01.x = v1.x * v0.x;  p01.y = fmaf(v1.x, v0.y, v1.y);
    p23.x = v3.x * v2.x;  p23.y = fmaf(v3.x, v2.y, v3.y);
    p.x = p23.x * p01.x;  p.y = fmaf(p23.x, p01.y, p23.y);

    #pragma unroll
    for (int off = 1; off < 32; off <<= 1) {
        float ap = __shfl_up_sync(0xffffffffu, p.x, off);
        float bp = __shfl_up_sync(0xffffffffu, p.y, off);
        if (lane >= off) {
            p.y = fmaf(p.x, bp, p.y);
            p.x = p.x * ap;
        }
    }
    float h = __shfl_up_sync(0xffffffffu, p.y, 1);
    if (lane == 0) h = 0.0f;

    chunkH[base + 0] = h;
    h = fmaf(v0.x, h, v0.y);
    chunkH[base + 1] = h;
    h = fmaf(v1.x, h, v1.y);
    chunkH[base + 2] = h;
    h = fmaf(v2.x, h, v2.y);
    chunkH[base + 3] = h;
}

// ---------------- scan phase 3: apply prefix, emit h ----------------
__global__ __launch_bounds__(Ddim) void scan_phase3(float* __restrict__ out)
{
    const int b = blockIdx.x >> 7;
    const int j = blockIdx.x & (NCHUNK - 1);
    const int d = threadIdx.x;
    const size_t base = ((size_t)b * Ldim + (size_t)j * CHUNK) * Ddim + d;
    const float* gp = g_gate + base;
    const float* cp = c_cand + base;
    float* op = out + base;

    float h = chunkH[((size_t)b * Ddim + d) * NCHUNK + j];
    #pragma unroll 4
    for (int t = 0; t < CHUNK; ++t) {
        float gv = gp[(size_t)t * Ddim];
        float cv = cp[(size_t)t * Ddim];
        h = fmaf(gv, cv - h, h);
        op[(size_t)t * Ddim] = h;
    }
}

// ---------------- launch ----------------
extern "C" void kernel_launch(void* const* d_in, const int* in_sizes, int n_in,
                              void* d_out, int out_size)
{
    const float* x  = (const float*)d_in[0];
    const float* Wg = (const float*)d_in[1];
    const float* bg = (const float*)d_in[2];
    const float* Wc = (const float*)d_in[3];
    const float* bc = (const float*)d_in[4];
    float* out = (float*)d_out;

    cudaFuncSetAttribute(gemm_act_kernel,
                         cudaFuncAttributeMaxDynamicSharedMemorySize, SMEM_BYTES);

    preround_kernel<<<512, 256>>>(Wg, Wc);
    dim3 gemm_grid(Ntot / BN, Mdim / BM);           // (8, 256) = 2048 CTAs
    gemm_act_kernel<<<gemm_grid, 256, SMEM_BYTES>>>(x, bg, bc);
    scan_phase1<<<Bdim * NCHUNK, Ddim>>>();         // 512 blocks
    scan_phase2<<<NCHAN / 8, 256>>>();
    scan_phase3<<<Bdim * NCHUNK, Ddim>>>(out);      // 512 blocks
}

// round 14
// speedup vs baseline: 2.0385x; 2.0385x over previous
#include <cuda_runtime.h>
#include <cuda_fp16.h>
#include <cstdint>
#include <math.h>

// Problem constants
#define Bdim 4
#define Ldim 8192
#define Ddim 512
#define Mdim (Bdim * Ldim)   // 32768
#define Ntot (2 * Ddim)      // 1024
#define Kdim 512

// GEMM tiling (mma.sync fp16 m16n8k16, cp.async 3-stage)
#define BM 256
#define BN 128
#define BK 64                            // k-halves per tile (128B rows)
#define NKT (Kdim / BK)                  // 8
#define KU (Kdim / 2)                    // 256 u32 per row of x_h / W_h
#define A_U32 (BM * 32)                  // 8192 u32 (32 u32/row)
#define B_U32 (BN * 32)                  // 4096 u32
#define STAGE_U32 (A_U32 + B_U32)        // 12288
#define NSTAGES 3
#define SMEM_BYTES (NSTAGES * STAGE_U32 * 4)   // 147456

// Scan config
#define CHUNK 64
#define NCHUNK (Ldim / CHUNK)        // 128
#define NCHAN (Bdim * Ddim)          // 2048

// ---------------- scratch ----------------
__device__ float g_gate[(size_t)Mdim * Ddim];
__device__ float c_cand[(size_t)Mdim * Ddim];
__device__ uint32_t x_h[(size_t)Mdim * KU];     // x in half2-packed
__device__ uint32_t W_h[(size_t)Ntot * KU];     // [Wg;Wc] in half2-packed
__device__ float2 chunkAB[(size_t)NCHAN * NCHUNK];
__device__ float  chunkH[(size_t)NCHAN * NCHUNK];

// ---------------- helpers ----------------
__device__ __forceinline__ uint32_t smem_u32(const void* p) {
    uint32_t a;
    asm("{ .reg .u64 t; cvta.to.shared.u64 t, %1; cvt.u32.u64 %0, t; }" : "=r"(a) : "l"(p));
    return a;
}
__device__ __forceinline__ uint32_t pack_h2(float lo, float hi) {
    uint32_t r;
    asm("{ .reg .b16 a, b;\n\t"
        "cvt.rn.f16.f32 a, %1;\n\t"
        "cvt.rn.f16.f32 b, %2;\n\t"
        "mov.b32 %0, {a, b}; }"
        : "=r"(r) : "f"(lo), "f"(hi));
    return r;
}
__device__ __forceinline__ void cp16(uint32_t dst, const void* src) {
    asm volatile("cp.async.cg.shared.global [%0], [%1], 16;" :: "r"(dst), "l"(src));
}
__device__ __forceinline__ void cp_commit() { asm volatile("cp.async.commit_group;" ::: "memory"); }
template <int N>
__device__ __forceinline__ void cp_wait() { asm volatile("cp.async.wait_group %0;" :: "n"(N) : "memory"); }

__device__ __forceinline__ void mma_f16(float c[4], const uint32_t a[4], const uint32_t b[2]) {
    asm volatile(
        "mma.sync.aligned.m16n8k16.row.col.f32.f16.f16.f32 "
        "{%0,%1,%2,%3}, {%4,%5,%6,%7}, {%8,%9}, {%0,%1,%2,%3};\n"
        : "+f"(c[0]), "+f"(c[1]), "+f"(c[2]), "+f"(c[3])
        : "r"(a[0]), "r"(a[1]), "r"(a[2]), "r"(a[3]), "r"(b[0]), "r"(b[1]));
}

// XOR-swizzled smem u32 index (row stride 32 u32 / 128B)
__device__ __forceinline__ int swz(int row, int col) {
    return (row << 5) + ((((col >> 2) ^ (row & 7)) << 2) | (col & 3));
}

// ---------------- convert x / W to fp16 ----------------
__global__ void convert_x_kernel(const float* __restrict__ x)
{
    size_t i = (size_t)blockIdx.x * 256 + threadIdx.x;   // float4 slots: 4.19M
    float4 v = reinterpret_cast<const float4*>(x)[i];
    uint2 o;
    o.x = pack_h2(v.x, v.y);
    o.y = pack_h2(v.z, v.w);
    reinterpret_cast<uint2*>(x_h)[i] = o;
}
__global__ void convert_w_kernel(const float* __restrict__ Wg, const float* __restrict__ Wc)
{
    int i = blockIdx.x * 256 + threadIdx.x;              // float4 slots: 262144
    const int half_n = (Ntot / 2) * Kdim / 4;            // 65536
    const float4* src = (i < half_n) ? (const float4*)Wg : (const float4*)Wc;
    int j = (i < half_n) ? i : i - half_n;
    float4 v = src[j];
    uint2 o;
    o.x = pack_h2(v.x, v.y);
    o.y = pack_h2(v.z, v.w);
    reinterpret_cast<uint2*>(W_h)[i] = o;
}

// ---------------- fused GEMM + activation ----------------
__global__ __launch_bounds__(512, 1) void gemm_act_kernel(
    const float* __restrict__ bg, const float* __restrict__ bc)
{
    extern __shared__ uint32_t smu[];
    const uint32_t smem_base = smem_u32(smu);

    const int m0 = blockIdx.y * BM;
    const int n0 = blockIdx.x * BN;
    const bool isGate = (n0 < Ddim);
    const uint32_t* Wp = W_h + (size_t)n0 * KU;

    const int tid  = threadIdx.x;
    const int warp = tid >> 5;
    const int lane = tid & 31;
    const int wm = warp >> 2;                // 0..3 -> 64 rows each
    const int wn = warp & 3;                 // 0..3 -> 32 cols each
    const int g  = lane >> 2;
    const int tg = lane & 3;

    // stage loader: A 2048 16B-chunks (4/thread), B 1024 (2/thread)
    auto load_stage = [&](int kt) {
        const uint32_t base  = smem_base + (kt % NSTAGES) * (STAGE_U32 * 4);
        const uint32_t bbase = base + A_U32 * 4;
        const int k0 = kt * 32;              // u32 offset in row
        #pragma unroll
        for (int r = 0; r < 4; ++r) {
            int i = tid + (r << 9);
            int row = i >> 3, j = i & 7;
            cp16(base + 4 * ((row << 5) + ((j ^ (row & 7)) << 2)),
                 x_h + (size_t)(m0 + row) * KU + k0 + j * 4);
        }
        #pragma unroll
        for (int r = 0; r < 2; ++r) {
            int i = tid + (r << 9);
            int row = i >> 3, j = i & 7;
            cp16(bbase + 4 * ((row << 5) + ((j ^ (row & 7)) << 2)),
                 Wp + (size_t)row * KU + k0 + j * 4);
        }
        cp_commit();
    };

    float acc[4][4][4];
    #pragma unroll
    for (int mt = 0; mt < 4; ++mt)
        #pragma unroll
        for (int nt = 0; nt < 4; ++nt)
            #pragma unroll
            for (int i = 0; i < 4; ++i) acc[mt][nt][i] = 0.0f;

    load_stage(0);
    load_stage(1);

    for (int s = 0; s < NKT; ++s) {
        if (s < NKT - 2) cp_wait<1>(); else cp_wait<0>();
        __syncthreads();

        const uint32_t* As = smu + (s % NSTAGES) * STAGE_U32;
        const uint32_t* Bs = As + A_U32;
        #pragma unroll
        for (int ks = 0; ks < 4; ++ks) {          // 4 slices of k16 (8 u32 cols)
            const int k = ks * 8;
            uint32_t af[4][4], bf[4][2];
            #pragma unroll
            for (int mt = 0; mt < 4; ++mt) {
                int r = wm * 64 + mt * 16;
                af[mt][0] = As[swz(r + g,     k + tg)];
                af[mt][1] = As[swz(r + g + 8, k + tg)];
                af[mt][2] = As[swz(r + g,     k + tg + 4)];
                af[mt][3] = As[swz(r + g + 8, k + tg + 4)];
            }
            #pragma unroll
            for (int nt = 0; nt < 4; ++nt) {
                int n = wn * 32 + nt * 8 + g;
                bf[nt][0] = Bs[swz(n, k + tg)];
                bf[nt][1] = Bs[swz(n, k + tg + 4)];
            }
            #pragma unroll
            for (int mt = 0; mt < 4; ++mt)
                #pragma unroll
                for (int nt = 0; nt < 4; ++nt)
                    mma_f16(acc[mt][nt], af[mt], bf[nt]);
        }
        __syncthreads();

        if (s + 2 < NKT) load_stage(s + 2);
    }

    // epilogue: bias + activation
    float* dst = isGate ? g_gate : c_cand;
    const float* bias = isGate ? bg : bc;
    const int cb = n0 & (Ddim - 1);
    #pragma unroll
    for (int mt = 0; mt < 4; ++mt) {
        #pragma unroll
        for (int nt = 0; nt < 4; ++nt) {
            int row0 = m0 + wm * 64 + mt * 16 + g;
            int col  = cb + wn * 32 + nt * 8 + 2 * tg;
            float b0v = bias[col], b1v = bias[col + 1];
            float2 o0, o1;
            if (isGate) {
                o0.x = 1.0f / (1.0f + expf(-(acc[mt][nt][0] + b0v)));
                o0.y = 1.0f / (1.0f + expf(-(acc[mt][nt][1] + b1v)));
                o1.x = 1.0f / (1.0f + expf(-(acc[mt][nt][2] + b0v)));
                o1.y = 1.0f / (1.0f + expf(-(acc[mt][nt][3] + b1v)));
            } else {
                o0.x = tanhf(acc[mt][nt][0] + b0v);
                o0.y = tanhf(acc[mt][nt][1] + b1v);
                o1.x = tanhf(acc[mt][nt][2] + b0v);
                o1.y = tanhf(acc[mt][nt][3] + b1v);
            }
            *reinterpret_cast<float2*>(&dst[(size_t)row0 * Ddim + col]) = o0;
            *reinterpret_cast<float2*>(&dst[(size_t)(row0 + 8) * Ddim + col]) = o1;
        }
    }
}

// ---------------- scan phase 1: per-chunk composed (A, B) ----------------
__global__ __launch_bounds__(Ddim) void scan_phase1(void)
{
    const int b = blockIdx.x >> 7;               // / NCHUNK
    const int j = blockIdx.x & (NCHUNK - 1);
    const int d = threadIdx.x;
    const size_t base = ((size_t)b * Ldim + (size_t)j * CHUNK) * Ddim + d;
    const float* gp = g_gate + base;
    const float* cp = c_cand + base;

    float A = 1.0f, Bv = 0.0f;
    #pragma unroll 4
    for (int t = 0; t < CHUNK; ++t) {
        float gv = gp[(size_t)t * Ddim];
        float cv = cp[(size_t)t * Ddim];
        float a = 1.0f - gv;
        Bv = fmaf(a, Bv, gv * cv);
        A  = a * A;
    }
    chunkAB[((size_t)b * Ddim + d) * NCHUNK + j] = make_float2(A, Bv);
}

// ---------------- scan phase 2: warp per channel, 128 chunks (4/lane) -----
__global__ __launch_bounds__(256) void scan_phase2(void)
{
    const int warp = threadIdx.x >> 5;
    const int lane = threadIdx.x & 31;
    const int ch = blockIdx.x * 8 + warp;
    const size_t base = (size_t)ch * NCHUNK + 4 * lane;

    float2 v0 = chunkAB[base + 0];
    float2 v1 = chunkAB[base + 1];
    float2 v2 = chunkAB[base + 2];
    float2 v3 = chunkAB[base + 3];
    float2 p01, p23, p;
    p01.x = v1.x * v0.x;  p01.y = fmaf(v1.x, v0.y, v1.y);
    p23.x = v3.x * v2.x;  p23.y = fmaf(v3.x, v2.y, v3.y);
    p.x = p23.x * p01.x;  p.y = fmaf(p23.x, p01.y, p23.y);

    #pragma unroll
    for (int off = 1; off < 32; off <<= 1) {
        float ap = __shfl_up_sync(0xffffffffu, p.x, off);
        float bp = __shfl_up_sync(0xffffffffu, p.y, off);
        if (lane >= off) {
            p.y = fmaf(p.x, bp, p.y);
            p.x = p.x * ap;
        }
    }
    float h = __shfl_up_sync(0xffffffffu, p.y, 1);
    if (lane == 0) h = 0.0f;

    chunkH[base + 0] = h;
    h = fmaf(v0.x, h, v0.y);
    chunkH[base + 1] = h;
    h = fmaf(v1.x, h, v1.y);
    chunkH[base + 2] = h;
    h = fmaf(v2.x, h, v2.y);
    chunkH[base + 3] = h;
}

// ---------------- scan phase 3: apply prefix, emit h ----------------
__global__ __launch_bounds__(Ddim) void scan_phase3(float* __restrict__ out)
{
    const int b = blockIdx.x >> 7;
    const int j = blockIdx.x & (NCHUNK - 1);
    const int d = threadIdx.x;
    const size_t base = ((size_t)b * Ldim + (size_t)j * CHUNK) * Ddim + d;
    const float* gp = g_gate + base;
    const float* cp = c_cand + base;
    float* op = out + base;

    float h = chunkH[((size_t)b * Ddim + d) * NCHUNK + j];
    #pragma unroll 4
    for (int t = 0; t < CHUNK; ++t) {
        float gv = gp[(size_t)t * Ddim];
        float cv = cp[(size_t)t * Ddim];
        h = fmaf(gv, cv - h, h);
        op[(size_t)t * Ddim] = h;
    }
}

// ---------------- launch ----------------
extern "C" void kernel_launch(void* const* d_in, const int* in_sizes, int n_in,
                              void* d_out, int out_size)
{
    const float* x  = (const float*)d_in[0];
    const float* Wg = (const float*)d_in[1];
    const float* bg = (const float*)d_in[2];
    const float* Wc = (const float*)d_in[3];
    const float* bc = (const float*)d_in[4];
    float* out = (float*)d_out;

    cudaFuncSetAttribute(gemm_act_kernel,
                         cudaFuncAttributeMaxDynamicSharedMemorySize, SMEM_BYTES);

    convert_x_kernel<<<(Mdim * Kdim / 4) / 256, 256>>>(x);      // 16384 blocks
    convert_w_kernel<<<(Ntot * Kdim / 4) / 256, 256>>>(Wg, Wc); // 1024 blocks
    dim3 gemm_grid(Ntot / BN, Mdim / BM);           // (8, 128) = 1024 CTAs
    gemm_act_kernel<<<gemm_grid, 512, SMEM_BYTES>>>(bg, bc);
    scan_phase1<<<Bdim * NCHUNK, Ddim>>>();         // 512 blocks
    scan_phase2<<<NCHAN / 8, 256>>>();
    scan_phase3<<<Bdim * NCHUNK, Ddim>>>(out);      // 512 blocks
}